// round 14
// baseline (speedup 1.0000x reference)
#include <cuda_runtime.h>
#include <cuda_bf16.h>

// CoscamLoss: B=4096 rows, C=16384 cols.
// d_in[0] = inputs        float32  [B, C]
// d_in[1] = targets       int32    [B]
// d_in[2] = mask          bool     [B, C]  (UNUSED by reference -> never read)
// d_in[3] = pos_cam_mask  float32  [B, C]
// d_out   = scalar float32 loss

#define B_ROWS   4096
#define C_COLS   16384
#define NTHREADS 512
#define NITERS   (C_COLS / 4 / NTHREADS)   // 8 float4-pairs per thread
#define GRID     304                       // 152 SMs x 2 resident CTAs (GB300)

__device__ float    g_rowloss[B_ROWS];
__device__ unsigned g_count = 0;           // self-resetting -> graph-replay safe

__device__ __forceinline__ float ex2(float x) {
    float y;
    asm("ex2.approx.ftz.f32 %0, %1;" : "=f"(y) : "f"(x));
    return y;
}

__global__ void __launch_bounds__(NTHREADS, 2)   // 64-reg budget, 32 warps/SM
coscam_row_kernel(const float* __restrict__ inputs,
                  const int*   __restrict__ targets,
                  const float* __restrict__ pos_mask,
                  float*       __restrict__ out)
{
    __shared__ float red_s[NTHREADS / 32];
    __shared__ bool  s_last;

    const int tid = threadIdx.x;

    // Fixed-shift logsumexp in log2 domain:
    //   non-hard: o = 16 v          -> t = v*(16*L2E)                - K*L2E
    //   hard:     o = 16.192 v+.192 -> t = v*(16.192*L2E) + .192*L2E - K*L2E
    //   term = 2^t = exp(o - K).  o in ~[-70, 70]: no overflow at K=80, and
    //   flushed terms are <= e^-110 relative to the max term: invisible.
    const float L2E = 1.44269504f;
    const float KC  = 80.0f;
    const float a0  = 16.0f   * L2E;
    const float b0  = -KC     * L2E;
    const float a1  = 16.192f * L2E;
    const float b1  = 0.192f  * L2E - KC * L2E;

    // Row-start state, prefetched one row ahead so the serial
    // targets[r] -> inputs[r,tgt] gather chain overlaps streaming work.
    int   r   = blockIdx.x;
    int   tgt = targets[r];
    float gt  = __ldg(&inputs[(size_t)r * C_COLS + tgt]);

    while (r < B_ROWS) {
        const int rn = r + GRID;
        int   tgt_n = 0;
        float gt_n  = 0.f;
        if (rn < B_ROWS) {
            tgt_n = targets[rn];
            gt_n  = __ldg(&inputs[(size_t)rn * C_COLS + tgt_n]);
        }

        const float4* in4 = (const float4*)(inputs   + (size_t)r * C_COLS) + tid;
        const float4* pm4 = (const float4*)(pos_mask + (size_t)r * C_COLS) + tid;

        float acc0 = 0.f, acc1 = 0.f, acc2 = 0.f, acc3 = 0.f;

        // R10 inner loop: depth-2, one (v,p) pair prefetched ahead.
        float4 v = in4[0];
        float4 p = pm4[0];
        #pragma unroll
        for (int i = 0; i < NITERS; i++) {
            float4 vn, pn;
            if (i + 1 < NITERS) {
                vn = in4[(i + 1) * NTHREADS];
                pn = pm4[(i + 1) * NTHREADS];
            }
            bool h;
            h = (p.x != 0.f) && (v.x >= gt);
            acc0 += ex2(fmaf(v.x, h ? a1 : a0, h ? b1 : b0));
            h = (p.y != 0.f) && (v.y >= gt);
            acc1 += ex2(fmaf(v.y, h ? a1 : a0, h ? b1 : b0));
            h = (p.z != 0.f) && (v.z >= gt);
            acc2 += ex2(fmaf(v.z, h ? a1 : a0, h ? b1 : b0));
            h = (p.w != 0.f) && (v.w >= gt);
            acc3 += ex2(fmaf(v.w, h ? a1 : a0, h ? b1 : b0));
            if (i + 1 < NITERS) { v = vn; p = pn; }
        }

        float s = (acc0 + acc1) + (acc2 + acc3);
        #pragma unroll
        for (int off = 16; off; off >>= 1)
            s += __shfl_xor_sync(0xffffffffu, s, off);
        if ((tid & 31) == 0) red_s[tid >> 5] = s;
        __syncthreads();

        if (tid == 0) {
            float ss = 0.f;
            #pragma unroll
            for (int w = 0; w < NTHREADS / 32; w++) ss += red_s[w];  // fixed order

            // Post-hoc target fix: the loop treated position tgt as a normal
            // element; its term is bitwise-reproducible here (same constants,
            // same fmaf/ex2 path, v = gt). Swap it for the true target term.
            const float pm_t = __ldg(&pos_mask[(size_t)r * C_COLS + tgt]);
            const bool  h    = (pm_t != 0.f);        // gt >= gt always true
            const float e_wrong = ex2(fmaf(gt, h ? a1 : a0, h ? b1 : b0));
            const float out_tgt = 16.0f * (gt - 0.1f);
            const float e_tgt   = ex2(fmaf(out_tgt, L2E, b0));
            ss = ss - e_wrong + e_tgt;

            // row loss = logsumexp(out) - out[tgt]
            g_rowloss[r] = (KC + logf(ss)) - out_tgt;
            __threadfence();
            unsigned t = atomicAdd(&g_count, 1u);
            s_last = (t == B_ROWS - 1u);
        }
        __syncthreads();

        // The CTA that completes the final row performs the deterministic mean.
        if (s_last) {
            __shared__ float red[NTHREADS / 32];
            float acc = 0.f;
            #pragma unroll
            for (int i = 0; i < B_ROWS / NTHREADS; i++)
                acc += g_rowloss[tid + i * NTHREADS];
            #pragma unroll
            for (int off = 16; off; off >>= 1)
                acc += __shfl_xor_sync(0xffffffffu, acc, off);
            if ((tid & 31) == 0) red[tid >> 5] = acc;
            __syncthreads();
            if (tid == 0) {
                float tot = 0.f;
                #pragma unroll
                for (int w = 0; w < NTHREADS / 32; w++) tot += red[w];
                out[0] = tot / (float)B_ROWS;
                g_count = 0;                   // reset for next replay
            }
        }

        r = rn; tgt = tgt_n; gt = gt_n;
    }
}

extern "C" void kernel_launch(void* const* d_in, const int* in_sizes, int n_in,
                              void* d_out, int out_size)
{
    const float* inputs   = (const float*)d_in[0];
    const int*   targets  = (const int*)d_in[1];
    // d_in[2] = mask (bool) — unused by the reference module
    const float* pos_mask = (const float*)d_in[3];
    float* out = (float*)d_out;

    coscam_row_kernel<<<GRID, NTHREADS>>>(inputs, targets, pos_mask, out);
}

// round 15
// speedup vs baseline: 1.1794x; 1.1794x over previous
#include <cuda_runtime.h>
#include <cuda_bf16.h>

// CoscamLoss: B=4096 rows, C=16384 cols.
// d_in[0] = inputs        float32  [B, C]
// d_in[1] = targets       int32    [B]
// d_in[2] = mask          bool     [B, C]  (UNUSED by reference -> never read)
// d_in[3] = pos_cam_mask  float32  [B, C]
// d_out   = scalar float32 loss

#define B_ROWS   4096
#define C_COLS   16384
#define NTHREADS 256
#define NITERS   (C_COLS / 4 / NTHREADS)   // 16 float4-pairs per thread

__device__ float    g_rowloss[B_ROWS];
__device__ unsigned g_count = 0;           // self-resetting -> graph-replay safe

__device__ __forceinline__ float ex2(float x) {
    float y;
    asm("ex2.approx.ftz.f32 %0, %1;" : "=f"(y) : "f"(x));
    return y;
}

__global__ void __launch_bounds__(NTHREADS, 4)   // 64-reg budget, 32 warps/SM, 4 CTAs/SM
coscam_row_kernel(const float* __restrict__ inputs,
                  const int*   __restrict__ targets,
                  const float* __restrict__ pos_mask,
                  float*       __restrict__ out)
{
    __shared__ float red_s[NTHREADS / 32];
    __shared__ bool  s_last;

    const int r   = blockIdx.x;
    const int tid = threadIdx.x;

    const float* in_row = inputs   + (size_t)r * C_COLS;
    const float* pm_row = pos_mask + (size_t)r * C_COLS;

    const int   tgt = targets[r];
    const float gt  = __ldg(&in_row[tgt]);
    // Hoisted: only tid 0 consumes pm_t (in the tail), but issuing the load
    // here hides its ~600-cycle latency under the streaming loop.
    float pm_t = 0.f;
    if (tid == 0) pm_t = __ldg(&pm_row[tgt]);

    // Fixed-shift logsumexp in log2 domain:
    //   non-hard: o = 16 v          -> t = v*(16*L2E)                - K*L2E
    //   hard:     o = 16.192 v+.192 -> t = v*(16.192*L2E) + .192*L2E - K*L2E
    //   term = 2^t = exp(o - K).  o in ~[-70, 70]: no overflow at K=80, and
    //   flushed terms are <= e^-110 relative to the max term: invisible.
    const float L2E = 1.44269504f;
    const float KC  = 80.0f;
    const float a0  = 16.0f   * L2E;
    const float b0  = -KC     * L2E;
    const float a1  = 16.192f * L2E;
    const float b1  = 0.192f  * L2E - KC * L2E;

    const float4* in4 = (const float4*)in_row + tid;
    const float4* pm4 = (const float4*)pm_row + tid;

    float acc0 = 0.f, acc1 = 0.f, acc2 = 0.f, acc3 = 0.f;

    // R10 inner loop shape: depth-2, one (v,p) pair prefetched ahead.
    float4 v = in4[0];
    float4 p = pm4[0];
    #pragma unroll
    for (int i = 0; i < NITERS; i++) {
        float4 vn, pn;
        if (i + 1 < NITERS) {
            vn = in4[(i + 1) * NTHREADS];
            pn = pm4[(i + 1) * NTHREADS];
        }
        bool h;
        h = (p.x != 0.f) && (v.x >= gt);
        acc0 += ex2(fmaf(v.x, h ? a1 : a0, h ? b1 : b0));
        h = (p.y != 0.f) && (v.y >= gt);
        acc1 += ex2(fmaf(v.y, h ? a1 : a0, h ? b1 : b0));
        h = (p.z != 0.f) && (v.z >= gt);
        acc2 += ex2(fmaf(v.z, h ? a1 : a0, h ? b1 : b0));
        h = (p.w != 0.f) && (v.w >= gt);
        acc3 += ex2(fmaf(v.w, h ? a1 : a0, h ? b1 : b0));
        if (i + 1 < NITERS) { v = vn; p = pn; }
    }

    float s = (acc0 + acc1) + (acc2 + acc3);
    #pragma unroll
    for (int off = 16; off; off >>= 1)
        s += __shfl_xor_sync(0xffffffffu, s, off);
    if ((tid & 31) == 0) red_s[tid >> 5] = s;
    __syncthreads();

    if (tid == 0) {
        float ss = 0.f;
        #pragma unroll
        for (int w = 0; w < NTHREADS / 32; w++) ss += red_s[w];  // fixed order

        // Post-hoc target fix: the loop treated position tgt as a normal
        // element; its term is bitwise-reproducible here (same constants,
        // same fmaf/ex2 path, v = gt). Swap it for the true target term.
        const bool  h    = (pm_t != 0.f);            // gt >= gt always true
        const float e_wrong = ex2(fmaf(gt, h ? a1 : a0, h ? b1 : b0));
        const float out_tgt = 16.0f * (gt - 0.1f);
        const float e_tgt   = ex2(fmaf(out_tgt, L2E, b0));
        ss = ss - e_wrong + e_tgt;

        // row loss = logsumexp(out) - out[tgt]
        g_rowloss[r] = (KC + __logf(ss)) - out_tgt;
        __threadfence();
        unsigned t = atomicAdd(&g_count, 1u);
        s_last = (t == B_ROWS - 1u);
    }
    __syncthreads();

    // Last CTA performs the deterministic fixed-order mean.
    if (s_last) {
        __shared__ float red[NTHREADS / 32];
        float acc = 0.f;
        #pragma unroll
        for (int i = 0; i < B_ROWS / NTHREADS; i++)
            acc += g_rowloss[tid + i * NTHREADS];
        #pragma unroll
        for (int off = 16; off; off >>= 1)
            acc += __shfl_xor_sync(0xffffffffu, acc, off);
        if ((tid & 31) == 0) red[tid >> 5] = acc;
        __syncthreads();
        if (tid == 0) {
            float tot = 0.f;
            #pragma unroll
            for (int w = 0; w < NTHREADS / 32; w++) tot += red[w];  // fixed order
            out[0] = tot / (float)B_ROWS;
            g_count = 0;                       // reset for next replay
        }
    }
}

extern "C" void kernel_launch(void* const* d_in, const int* in_sizes, int n_in,
                              void* d_out, int out_size)
{
    const float* inputs   = (const float*)d_in[0];
    const int*   targets  = (const int*)d_in[1];
    // d_in[2] = mask (bool) — unused by the reference module
    const float* pos_mask = (const float*)d_in[3];
    float* out = (float*)d_out;

    coscam_row_kernel<<<B_ROWS, NTHREADS>>>(inputs, targets, pos_mask, out);
}